// round 4
// baseline (speedup 1.0000x reference)
#include <cuda_runtime.h>

typedef unsigned long long ull;

#define NB   64
#define CC   64
#define TT   300
#define VV   25
#define TV   7500
#define ICn  16
#define OCn  64
#define KS   3
#define KT   9
#define YSZ  30720000
#define BN_CNT 480000.0f

// ---------------- f32x2 helpers (FFMA2) ----------------
__device__ __forceinline__ ull fma2(ull a, ull b, ull c) {
    ull d;
    asm("fma.rn.f32x2 %0,%1,%2,%3;" : "=l"(d) : "l"(a), "l"(b), "l"(c));
    return d;
}
__device__ __forceinline__ ull dup2(float v) {
    ull d; asm("mov.b64 %0,{%1,%1};" : "=l"(d) : "f"(v)); return d;
}
__device__ __forceinline__ float2 unpk(ull a) {
    float2 r; asm("mov.b64 {%0,%1},%2;" : "=f"(r.x), "=f"(r.y) : "l"(a)); return r;
}

// ---------------- scratch ----------------
__device__ float g_fa[KS*NB*ICn*TV];
__device__ float g_fb[KS*NB*ICn*TV];
__device__ float g_S [KS*NB*VV*VV];
__device__ float g_y1[(size_t)NB*OCn*TV];
__device__ float g_ps[NB*OCn];
__device__ float g_pq[NB*OCn];
__device__ float g_stats[4*OCn];

// ---------------- K1: fa/fb 1x1 projections (f32x2, row-pair packed) --------
__global__ void __launch_bounds__(256) k_projab(const float* __restrict__ x,
        const float* __restrict__ Wa, const float* __restrict__ ba,
        const float* __restrict__ Wb, const float* __restrict__ bb) {
    __shared__ __align__(16) float ws2[64*96];
    int tid = threadIdx.x;
    for (int i = tid; i < 48*64; i += 256) {
        int r = i >> 6, c = i & 63;
        ws2[c*96 + r]      = Wa[i];
        ws2[c*96 + 48 + r] = Wb[i];
    }
    __syncthreads();
    int n = blockIdx.y;
    int base = blockIdx.x * 1024 + tid;
    const float* xn = x + n * CC * TV;

    for (int p = 0; p < 6; p++) {
        ull acc2[8][4];
        #pragma unroll
        for (int jj = 0; jj < 8; jj++)
            #pragma unroll
            for (int m = 0; m < 4; m++) acc2[jj][m] = 0ull;
        #pragma unroll 2
        for (int c = 0; c < 64; c++) {
            ull xd[4];
            #pragma unroll
            for (int m = 0; m < 4; m++) {
                int tv = base + m * 256;
                xd[m] = dup2((tv < TV) ? xn[c * TV + tv] : 0.f);
            }
            const ull* wp = (const ull*)(ws2 + c*96 + p*16);
            #pragma unroll
            for (int jj = 0; jj < 8; jj++) {
                ull w2 = wp[jj];
                #pragma unroll
                for (int m = 0; m < 4; m++) acc2[jj][m] = fma2(w2, xd[m], acc2[jj][m]);
            }
        }
        #pragma unroll
        for (int jj = 0; jj < 8; jj++) {
            #pragma unroll
            for (int h = 0; h < 2; h++) {
                int r = p*16 + 2*jj + h;
                float bias; float* out;
                if (r < 48) {
                    bias = ba[r];
                    out = g_fa + ((r >> 4) * NB * ICn + n * ICn + (r & 15)) * TV;
                } else {
                    int r2 = r - 48;
                    bias = bb[r2];
                    out = g_fb + ((r2 >> 4) * NB * ICn + n * ICn + (r2 & 15)) * TV;
                }
                #pragma unroll
                for (int m = 0; m < 4; m++) {
                    int tv = base + m * 256;
                    if (tv < TV) {
                        float2 f = unpk(acc2[jj][m]);
                        out[tv] = (h ? f.y : f.x) + bias;
                    }
                }
            }
        }
    }
}

// ---------------- K2: attention scores + softmax + A (transposed, f32x2) ----
// aT[v][d], bT[w][d] with row pad 66 -> d-pairs are LDS.64; accumulate pairwise.
__global__ void k_scoreS(const float* __restrict__ adj, const float* __restrict__ PA) {
    int kk = blockIdx.x / NB, n = blockIdx.x % NB;
    const float* fa = g_fa + (kk * NB * ICn + n * ICn) * TV;
    const float* fb = g_fb + (kk * NB * ICn + n * ICn) * TV;
    __shared__ __align__(16) float aT[25*66], bT[25*66];
    __shared__ float Ssm[625];
    int tid = threadIdx.x;                 // 640 threads
    int v = tid / 25, w = tid - v * 25;
    bool act = tid < 625;
    ull acc2 = 0ull;
    for (int d0 = 0; d0 < 4800; d0 += 64) {
        for (int i = tid; i < 1600; i += 640) {
            int d = i / 25, vv = i - d * 25;
            float av = fa[d0 * 25 + i];
            float bv = fb[d0 * 25 + i];
            aT[vv * 66 + d] = av;
            bT[vv * 66 + d] = bv;
        }
        __syncthreads();
        if (act) {
            const ull* ap = (const ull*)(aT + v * 66);
            const ull* bp = (const ull*)(bT + w * 66);
            #pragma unroll 8
            for (int d2 = 0; d2 < 32; d2++) acc2 = fma2(ap[d2], bp[d2], acc2);
        }
        __syncthreads();
    }
    if (act) {
        float2 f = unpk(acc2);
        Ssm[tid] = (f.x + f.y) * (1.f / 4800.f);
    }
    __syncthreads();
    if (tid < 25) {
        int wq = tid;
        float m = -1e30f;
        #pragma unroll
        for (int vi = 0; vi < 25; vi++) m = fmaxf(m, Ssm[vi*25 + wq]);
        float e[25]; float s = 0.f;
        #pragma unroll
        for (int vi = 0; vi < 25; vi++) { e[vi] = expf(Ssm[vi*25 + wq] - m); s += e[vi]; }
        float inv = 1.f / s;
        #pragma unroll
        for (int vi = 0; vi < 25; vi++) {
            int ai = (kk * VV + vi) * VV + wq;
            g_S[(kk * NB + n) * 625 + vi * 25 + wq] = e[vi] * inv + adj[ai] + PA[ai];
        }
    }
}

// ---------------- K3: fused GCN (x·S mix + Wd projection), 512 threads ------
#define GC_S   0                   // S padded [3][25][26] = 2028
#define GC_W   2028                // Wd [kc][o]           = 12288
#define GC_X   14316               // x  [c][100]          = 6400
#define GC_Z   20716               // Z  [kc][100] + pad   = 19328
#define GC_TOT 40044               // floats (160176 bytes)
__global__ void __launch_bounds__(512) k_gcn(const float* __restrict__ x,
        const float* __restrict__ Wd, const float* __restrict__ bd) {
    extern __shared__ float sm[];
    float* S_s  = sm + GC_S;
    float* Wd_s = sm + GC_W;
    float* x_s  = sm + GC_X;
    float* Z_s  = sm + GC_Z;
    int tid = threadIdx.x;
    int n = blockIdx.y;
    int tile0 = blockIdx.x * 100;

    for (int i = tid; i < 1875; i += 512) {
        int k = i / 625, r = i - k * 625;
        int v = r / 25, w = r - v * 25;
        S_s[k*650 + v*26 + w] = g_S[(k * NB + n) * 625 + r];
    }
    for (int i = tid; i < 75; i += 512) {
        int k = i / 25, v = i - k * 25;
        S_s[k*650 + v*26 + 25] = 0.f;
    }
    for (int i = tid; i < 12288; i += 512) {
        int kc = i >> 6, o = i & 63;
        int k = kc >> 6, c = kc & 63;
        Wd_s[i] = Wd[(k*64 + o)*64 + c];
    }
    for (int i = tid; i < 6400; i += 512) {
        int c = i / 100, j = i - c * 100;
        x_s[i] = x[(n * CC + c) * TV + tile0 + j];
    }
    __syncthreads();

    // ---- mixing: Z[kc, t*25+w] = sum_v x[c, t*25+v] * S[k, v, w] ----
    for (int r = 0; r < 2; r++) {
        int task = r * 512 + tid;          // 768 tasks = 192 kc x 4 t
        if (task < 768) {
            int kc = task >> 2, t = task & 3;
            int k = kc >> 6, c = kc & 63;
            ull acc2[13];
            #pragma unroll
            for (int p = 0; p < 13; p++) acc2[p] = 0ull;
            const float* xrow = x_s + c * 100 + t * 25;
            const float* Srow = S_s + k * 650;
            #pragma unroll 5
            for (int v = 0; v < 25; v++) {
                ull xd = dup2(xrow[v]);
                const ull* sp = (const ull*)(Srow + v * 26);
                #pragma unroll
                for (int p = 0; p < 13; p++) acc2[p] = fma2(sp[p], xd, acc2[p]);
            }
            float* zr = Z_s + kc * 100 + t * 25;
            #pragma unroll
            for (int p = 0; p < 12; p++) {
                float2 f = unpk(acc2[p]);
                zr[2*p] = f.x; zr[2*p+1] = f.y;
            }
            zr[24] = unpk(acc2[12]).x;
        }
    }
    __syncthreads();

    // ---- projection: y[o, j] = sum_kc Wd[kc,o] * Z[kc,j] ----
    // 16 warps: warp (ty&7) -> 8 o's; (ty>>3) selects tw half (m pair).
    int ty = tid >> 5, tx = tid & 31;
    int ob = (ty & 7) * 8;
    int mbase = (ty >> 3) * 2;
    ull acc2[4][2];
    #pragma unroll
    for (int a = 0; a < 4; a++) { acc2[a][0] = 0ull; acc2[a][1] = 0ull; }
    #pragma unroll 4
    for (int kc = 0; kc < 192; kc++) {
        ull zd[2];
        #pragma unroll
        for (int m = 0; m < 2; m++) zd[m] = dup2(Z_s[kc*100 + tx + 32*(mbase+m)]);
        const ull* wp = (const ull*)(Wd_s + kc*64 + ob);
        #pragma unroll
        for (int a = 0; a < 4; a++) {
            ull w2 = wp[a];
            acc2[a][0] = fma2(w2, zd[0], acc2[a][0]);
            acc2[a][1] = fma2(w2, zd[1], acc2[a][1]);
        }
    }
    #pragma unroll
    for (int a = 0; a < 4; a++) {
        int o0 = ob + 2*a;
        float b0 = bd[o0]   + bd[64+o0]   + bd[128+o0];
        float b1 = bd[o0+1] + bd[64+o0+1] + bd[128+o0+1];
        #pragma unroll
        for (int m = 0; m < 2; m++) {
            int j = tx + 32*(mbase+m);
            if (j < 100) {
                float2 f = unpk(acc2[a][m]);
                g_y1[(size_t)(n*OCn + o0  ) * TV + tile0 + j] = f.x + b0;
                g_y1[(size_t)(n*OCn + o0+1) * TV + tile0 + j] = f.y + b1;
            }
        }
    }
}

// ---------------- BN stats (deterministic 2-stage) ----------------
__device__ __forceinline__ void bn_part_body(const float* p) {
    float s = 0.f, q = 0.f;
    for (int i = threadIdx.x; i < TV; i += 256) { float v = p[i]; s += v; q = fmaf(v, v, q); }
    __shared__ float sh[512];
    sh[threadIdx.x] = s; sh[256 + threadIdx.x] = q;
    __syncthreads();
    for (int st = 128; st; st >>= 1) {
        if (threadIdx.x < st) {
            sh[threadIdx.x] += sh[threadIdx.x + st];
            sh[256 + threadIdx.x] += sh[256 + threadIdx.x + st];
        }
        __syncthreads();
    }
    if (threadIdx.x == 0) {
        int n = blockIdx.x, o = blockIdx.y;
        g_ps[o * 64 + n] = sh[0];
        g_pq[o * 64 + n] = sh[256];
    }
}
__global__ void k_part_y1() { bn_part_body(g_y1 + (size_t)(blockIdx.x * 64 + blockIdx.y) * TV); }
__global__ void k_part_src(const float* __restrict__ s) { bn_part_body(s + (size_t)(blockIdx.x * 64 + blockIdx.y) * TV); }

__global__ void k_bnfinal(int off) {
    int o = threadIdx.x;
    if (o < 64) {
        float s = 0.f, q = 0.f;
        for (int n = 0; n < 64; n++) { s += g_ps[o * 64 + n]; q += g_pq[o * 64 + n]; }
        g_stats[off + o] = s;
        g_stats[off + 64 + o] = q;
    }
}

// ---------------- K6: temporal conv, f32x2, BN1+residual+relu fused on load -
__global__ void __launch_bounds__(256) k_tcn(const float* __restrict__ Wt,
                                             const float* __restrict__ bt,
                                             const float* __restrict__ x,
                                             const float* __restrict__ g1,
                                             const float* __restrict__ b1,
                                             float* __restrict__ out) {
    __shared__ float ys[8 * 456];
    __shared__ __align__(16) float wsm[8 * 9 * 64];
    __shared__ float csc[64], csh[64];
    int n = blockIdx.y;
    int tile0 = blockIdx.x * 256;
    int tid = threadIdx.x;
    int ty = tid >> 5, tx = tid & 31;
    int ob = ty * 8;
    if (tid < 64) {
        const float inv = 1.f / BN_CNT;
        float mu  = g_stats[tid] * inv;
        float var = fmaf(-mu, mu, g_stats[64 + tid] * inv);
        float sc  = rsqrtf(var + 1e-5f) * g1[tid];
        csc[tid] = sc;
        csh[tid] = fmaf(-mu, sc, b1[tid]);
    }
    ull acc2[4][8];
    #pragma unroll
    for (int a = 0; a < 4; a++)
        #pragma unroll
        for (int j = 0; j < 8; j++) acc2[a][j] = 0ull;
    __syncthreads();

    for (int c0 = 0; c0 < 64; c0 += 8) {
        __syncthreads();
        for (int i = tid; i < 8 * 456; i += 256) {
            int c = i / 456, off = i - c * 456;
            int tw = tile0 - 100 + off;
            int cc = c0 + c;
            float v = 0.f;
            if (tw >= 0 && tw < TV) {
                int gi = (n * CC + cc) * TV + tw;
                float raw = g_y1[gi];
                v = fmaf(raw, csc[cc], csh[cc]) + x[gi];
                v = fmaxf(v, 0.f);
            }
            ys[i] = v;
        }
        for (int i = tid; i < 8 * 9 * 64; i += 256) {
            int o = i & 63, ck = i >> 6;
            int c = ck / 9, kt = ck - c * 9;
            wsm[i] = Wt[(o * 64 + c0 + c) * 9 + kt];
        }
        __syncthreads();
        for (int c = 0; c < 8; c++) {
            #pragma unroll 3
            for (int kt = 0; kt < 9; kt++) {
                int ybase = c * 456 + 100 + 25 * (kt - 4) + tx;
                ull yd[8];
                #pragma unroll
                for (int j = 0; j < 8; j++) yd[j] = dup2(ys[ybase + 32 * j]);
                const ull* wp = (const ull*)(wsm + (c * 9 + kt) * 64 + ob);
                #pragma unroll
                for (int a = 0; a < 4; a++) {
                    ull w2 = wp[a];
                    #pragma unroll
                    for (int j = 0; j < 8; j++)
                        acc2[a][j] = fma2(w2, yd[j], acc2[a][j]);
                }
            }
        }
    }
    #pragma unroll
    for (int a = 0; a < 4; a++) {
        int o0 = ob + 2*a;
        float b0 = bt[o0], b1v = bt[o0+1];
        #pragma unroll
        for (int j = 0; j < 8; j++) {
            int tw = tile0 + tx + 32 * j;
            if (tw < TV) {
                float2 f = unpk(acc2[a][j]);
                out[(size_t)(n * OCn + o0  ) * TV + tw] = f.x + b0;
                out[(size_t)(n * OCn + o0+1) * TV + tw] = f.y + b1v;
            }
        }
    }
}

// ---------------- BN2 apply + residual + relu ----------------
__global__ void k_bn2(float* __restrict__ out, const float* __restrict__ x,
                      const float* __restrict__ g2, const float* __restrict__ b2) {
    int idx = blockIdx.x * 256 + threadIdx.x;
    if (idx >= YSZ) return;
    int c = (idx / TV) & 63;
    const float inv = 1.f / BN_CNT;
    float mu  = g_stats[128 + c] * inv;
    float var = fmaf(-mu, mu, g_stats[192 + c] * inv);
    float sc  = rsqrtf(var + 1e-5f) * g2[c];
    float v   = (out[idx] - mu) * sc + b2[c] + x[idx];
    out[idx] = fmaxf(v, 0.f);
}

// ---------------- adj passthrough ----------------
__global__ void k_copyadj(const float* __restrict__ adj, float* __restrict__ out, int count) {
    int i = blockIdx.x * 256 + threadIdx.x;
    if (i < count) out[YSZ + i] = adj[i];
}

// ---------------- launch ----------------
extern "C" void kernel_launch(void* const* d_in, const int* in_sizes, int n_in,
                              void* d_out, int out_size) {
    const float* x   = (const float*)d_in[0];
    const float* adj = (const float*)d_in[1];
    const float* PA  = (const float*)d_in[2];
    const float* Wa  = (const float*)d_in[3];
    const float* ba  = (const float*)d_in[4];
    const float* Wb  = (const float*)d_in[5];
    const float* bb  = (const float*)d_in[6];
    const float* Wd  = (const float*)d_in[7];
    const float* bd  = (const float*)d_in[8];
    const float* g1  = (const float*)d_in[9];
    const float* b1  = (const float*)d_in[10];
    const float* Wt  = (const float*)d_in[11];
    const float* bt  = (const float*)d_in[12];
    const float* g2  = (const float*)d_in[13];
    const float* b2  = (const float*)d_in[14];
    float* out = (float*)d_out;

    static int smem_set = 0;
    if (!smem_set) {
        cudaFuncSetAttribute(k_gcn, cudaFuncAttributeMaxDynamicSharedMemorySize,
                             GC_TOT * sizeof(float));
        smem_set = 1;
    }

    // copyadj first so the profiler's fixed 4th-launch capture lands on k_gcn
    int adjcount = out_size - YSZ;
    if (adjcount > 0) {
        if (adjcount > 3 * VV * VV) adjcount = 3 * VV * VV;
        k_copyadj<<<8, 256>>>(adj, out, adjcount);
    }

    k_projab<<<dim3(8, 64), 256>>>(x, Wa, ba, Wb, bb);
    k_scoreS<<<192, 640>>>(adj, PA);
    k_gcn<<<dim3(75, 64), 512, GC_TOT * sizeof(float)>>>(x, Wd, bd);

    k_part_y1<<<dim3(64, 64), 256>>>();
    k_bnfinal<<<1, 64>>>(0);

    k_tcn<<<dim3(30, 64), 256>>>(Wt, bt, x, g1, b1, out);

    k_part_src<<<dim3(64, 64), 256>>>(out);
    k_bnfinal<<<1, 64>>>(128);
    k_bn2<<<(YSZ + 255) / 256, 256>>>(out, x, g2, b2);
}

// round 5
// speedup vs baseline: 1.0186x; 1.0186x over previous
#include <cuda_runtime.h>

typedef unsigned long long ull;

#define NB   64
#define CC   64
#define TT   300
#define VV   25
#define TV   7500
#define ICn  16
#define OCn  64
#define KS   3
#define KT   9
#define YSZ  30720000
#define BN_CNT 480000.0f

// ---------------- f32x2 helpers (FFMA2) ----------------
__device__ __forceinline__ ull fma2(ull a, ull b, ull c) {
    ull d;
    asm("fma.rn.f32x2 %0,%1,%2,%3;" : "=l"(d) : "l"(a), "l"(b), "l"(c));
    return d;
}
__device__ __forceinline__ ull dup2(float v) {
    ull d; asm("mov.b64 %0,{%1,%1};" : "=l"(d) : "f"(v)); return d;
}
__device__ __forceinline__ float2 unpk(ull a) {
    float2 r; asm("mov.b64 {%0,%1},%2;" : "=f"(r.x), "=f"(r.y) : "l"(a)); return r;
}
__device__ __forceinline__ float wredsum(float v) {
    #pragma unroll
    for (int s = 16; s; s >>= 1) v += __shfl_xor_sync(0xffffffffu, v, s);
    return v;
}

// ---------------- scratch ----------------
__device__ float g_fa[KS*NB*ICn*TV];
__device__ float g_fb[KS*NB*ICn*TV];
__device__ float g_S [KS*NB*VV*VV];
__device__ float g_y1[(size_t)NB*OCn*TV];
__device__ float g_ps1[64*9600];
__device__ float g_pq1[64*9600];
__device__ float g_ps2[64*1920];
__device__ float g_pq2[64*1920];
__device__ float g_stats[4*OCn];

// ---------------- K1: fa/fb 1x1 projections (f32x2, row-pair packed) --------
__global__ void __launch_bounds__(256) k_projab(const float* __restrict__ x,
        const float* __restrict__ Wa, const float* __restrict__ ba,
        const float* __restrict__ Wb, const float* __restrict__ bb) {
    __shared__ __align__(16) float ws2[64*96];
    int tid = threadIdx.x;
    for (int i = tid; i < 48*64; i += 256) {
        int r = i >> 6, c = i & 63;
        ws2[c*96 + r]      = Wa[i];
        ws2[c*96 + 48 + r] = Wb[i];
    }
    __syncthreads();
    int n = blockIdx.y;
    int base = blockIdx.x * 1024 + tid;
    const float* xn = x + n * CC * TV;

    for (int p = 0; p < 6; p++) {
        ull acc2[8][4];
        #pragma unroll
        for (int jj = 0; jj < 8; jj++)
            #pragma unroll
            for (int m = 0; m < 4; m++) acc2[jj][m] = 0ull;
        #pragma unroll 2
        for (int c = 0; c < 64; c++) {
            ull xd[4];
            #pragma unroll
            for (int m = 0; m < 4; m++) {
                int tv = base + m * 256;
                xd[m] = dup2((tv < TV) ? xn[c * TV + tv] : 0.f);
            }
            const ull* wp = (const ull*)(ws2 + c*96 + p*16);
            #pragma unroll
            for (int jj = 0; jj < 8; jj++) {
                ull w2 = wp[jj];
                #pragma unroll
                for (int m = 0; m < 4; m++) acc2[jj][m] = fma2(w2, xd[m], acc2[jj][m]);
            }
        }
        #pragma unroll
        for (int jj = 0; jj < 8; jj++) {
            #pragma unroll
            for (int h = 0; h < 2; h++) {
                int r = p*16 + 2*jj + h;
                float bias; float* out;
                if (r < 48) {
                    bias = ba[r];
                    out = g_fa + ((r >> 4) * NB * ICn + n * ICn + (r & 15)) * TV;
                } else {
                    int r2 = r - 48;
                    bias = bb[r2];
                    out = g_fb + ((r2 >> 4) * NB * ICn + n * ICn + (r2 & 15)) * TV;
                }
                #pragma unroll
                for (int m = 0; m < 4; m++) {
                    int tv = base + m * 256;
                    if (tv < TV) {
                        float2 f = unpk(acc2[jj][m]);
                        out[tv] = (h ? f.y : f.x) + bias;
                    }
                }
            }
        }
    }
}

// ---------------- K2: attention scores + softmax + A (R2 known-good) --------
__global__ void k_scoreS(const float* __restrict__ adj, const float* __restrict__ PA) {
    int kk = blockIdx.x / NB, n = blockIdx.x % NB;
    const float* fa = g_fa + (kk * NB * ICn + n * ICn) * TV;
    const float* fb = g_fb + (kk * NB * ICn + n * ICn) * TV;
    __shared__ float as[64*25], bs[64*25], Ssm[625];
    int tid = threadIdx.x;                 // 640 threads
    int v = tid / 25, w = tid - v * 25;
    bool act = tid < 625;
    float acc = 0.f;
    for (int d0 = 0; d0 < 4800; d0 += 64) {
        for (int i = tid; i < 1600; i += 640) {
            as[i] = fa[d0 * 25 + i];
            bs[i] = fb[d0 * 25 + i];
        }
        __syncthreads();
        if (act) {
            #pragma unroll 8
            for (int d = 0; d < 64; d++) acc = fmaf(as[d*25 + v], bs[d*25 + w], acc);
        }
        __syncthreads();
    }
    if (act) Ssm[tid] = acc * (1.f / 4800.f);
    __syncthreads();
    if (tid < 25) {
        int wq = tid;
        float m = -1e30f;
        #pragma unroll
        for (int vi = 0; vi < 25; vi++) m = fmaxf(m, Ssm[vi*25 + wq]);
        float e[25]; float s = 0.f;
        #pragma unroll
        for (int vi = 0; vi < 25; vi++) { e[vi] = expf(Ssm[vi*25 + wq] - m); s += e[vi]; }
        float inv = 1.f / s;
        #pragma unroll
        for (int vi = 0; vi < 25; vi++) {
            int ai = (kk * VV + vi) * VV + wq;
            g_S[(kk * NB + n) * 625 + vi * 25 + wq] = e[vi] * inv + adj[ai] + PA[ai];
        }
    }
}

// ---------------- K3: fused GCN v2 — tile 50 tw, 2 CTAs/SM, LDS.128 ---------
// S padded [3][25][28] (16B-aligned rows), x stride 51, Z stride 53 (odd:
// conflict-free). Mixing: thread = kc (192 active), 26 f32x2 accumulators,
// S row reads are warp-broadcast LDS.128. Projection: warp = 8 o (2 LDS.128
// of weights), lanes + m cover 50 tw. BN1 partial sums fused in epilogue.
#define GS_S   0
#define GS_W   2100
#define GS_X   14388
#define GS_Z   17652
#define GS_TOT 27828      // floats = 111,312 bytes
__global__ void __launch_bounds__(256) k_gcn(const float* __restrict__ x,
        const float* __restrict__ Wd, const float* __restrict__ bd) {
    extern __shared__ __align__(16) float sm[];
    float* S_s  = sm + GS_S;     // [k*700 + v*28 + w]
    float* Wd_s = sm + GS_W;     // [kc*64 + o]
    float* x_s  = sm + GS_X;     // [c*51 + j], j<50
    float* Z_s  = sm + GS_Z;     // [kc*53 + j], j<50
    int tid = threadIdx.x;
    int n = blockIdx.y;
    int tile0 = blockIdx.x * 50;

    for (int i = tid; i < 1875; i += 256) {
        int k = i / 625, r = i - k * 625;
        int v = r / 25, w = r - v * 25;
        S_s[k*700 + v*28 + w] = g_S[(k * NB + n) * 625 + r];
    }
    for (int i = tid; i < 225; i += 256) {           // zero pads w=25..27
        int k = i / 75, rr = i - k * 75;
        int v = rr / 3, pw = rr - v * 3;
        S_s[k*700 + v*28 + 25 + pw] = 0.f;
    }
    for (int i = tid; i < 12288; i += 256) {
        int kc = i >> 6, o = i & 63;
        int k = kc >> 6, c = kc & 63;
        Wd_s[i] = Wd[(k*64 + o)*64 + c];
    }
    for (int i = tid; i < 3200; i += 256) {
        int c = i / 50, j = i - c * 50;
        x_s[c*51 + j] = x[(n * CC + c) * TV + tile0 + j];
    }
    __syncthreads();

    // ---- mixing: Z[kc, t*25+w] = sum_v x[c, t*25+v] * S[k, v, w] ----
    if (tid < 192) {
        int kc = tid, k = kc >> 6, c = kc & 63;
        ull acc[26];
        #pragma unroll
        for (int p = 0; p < 26; p++) acc[p] = 0ull;
        const float* xrow = x_s + c * 51;
        const float* Srow = S_s + k * 700;
        #pragma unroll 5
        for (int v = 0; v < 25; v++) {
            ull xd0 = dup2(xrow[v]);
            ull xd1 = dup2(xrow[25 + v]);
            const ulonglong2* sp2 = (const ulonglong2*)(Srow + v * 28);
            ull sv[13];
            #pragma unroll
            for (int q = 0; q < 6; q++) {
                ulonglong2 u = sp2[q];
                sv[2*q] = u.x; sv[2*q+1] = u.y;
            }
            sv[12] = ((const ull*)(Srow + v * 28))[6];
            #pragma unroll
            for (int p = 0; p < 13; p++) {
                acc[p]      = fma2(sv[p], xd0, acc[p]);
                acc[13 + p] = fma2(sv[p], xd1, acc[13 + p]);
            }
        }
        float* zr = Z_s + kc * 53;
        #pragma unroll
        for (int p = 0; p < 12; p++) {
            float2 f0 = unpk(acc[p]);
            float2 f1 = unpk(acc[13 + p]);
            zr[2*p] = f0.x; zr[2*p+1] = f0.y;
            zr[25 + 2*p] = f1.x; zr[25 + 2*p + 1] = f1.y;
        }
        zr[24] = unpk(acc[12]).x;
        zr[49] = unpk(acc[25]).x;
    }
    __syncthreads();

    // ---- projection: y[o, j] = sum_kc Wd[kc,o] * Z[kc,j] + bias ----
    int ty = tid >> 5, tx = tid & 31;
    int ob = ty * 8;
    ull acc2[4][2];
    #pragma unroll
    for (int a = 0; a < 4; a++) { acc2[a][0] = 0ull; acc2[a][1] = 0ull; }
    #pragma unroll 4
    for (int kc = 0; kc < 192; kc++) {
        const ulonglong2* wp2 = (const ulonglong2*)(Wd_s + kc*64 + ob);
        ulonglong2 wA = wp2[0];
        ulonglong2 wB = wp2[1];
        ull z0 = dup2(Z_s[kc*53 + tx]);
        ull z1 = dup2(Z_s[kc*53 + 32 + tx]);
        acc2[0][0] = fma2(wA.x, z0, acc2[0][0]);
        acc2[0][1] = fma2(wA.x, z1, acc2[0][1]);
        acc2[1][0] = fma2(wA.y, z0, acc2[1][0]);
        acc2[1][1] = fma2(wA.y, z1, acc2[1][1]);
        acc2[2][0] = fma2(wB.x, z0, acc2[2][0]);
        acc2[2][1] = fma2(wB.x, z1, acc2[2][1]);
        acc2[3][0] = fma2(wB.y, z0, acc2[3][0]);
        acc2[3][1] = fma2(wB.y, z1, acc2[3][1]);
    }
    int blk = n * 150 + blockIdx.x;
    bool v1 = (tx < 18);                       // j = 32+tx < 50
    #pragma unroll
    for (int a = 0; a < 4; a++) {
        int o0 = ob + 2*a;
        float b0 = bd[o0]   + bd[64+o0]   + bd[128+o0];
        float b1 = bd[o0+1] + bd[64+o0+1] + bd[128+o0+1];
        float2 f0 = unpk(acc2[a][0]);
        float2 f1 = unpk(acc2[a][1]);
        float vx0 = f0.x + b0, vy0 = f0.y + b1;
        float vx1 = f1.x + b0, vy1 = f1.y + b1;
        size_t base0 = (size_t)(n*OCn + o0) * TV + tile0;
        g_y1[base0 + tx] = vx0;
        g_y1[base0 + TV + tx] = vy0;
        if (v1) {
            g_y1[base0 + 32 + tx] = vx1;
            g_y1[base0 + TV + 32 + tx] = vy1;
        }
        // BN1 partial sums (deterministic warp tree)
        float sx = vx0 + (v1 ? vx1 : 0.f);
        float qx = vx0*vx0 + (v1 ? vx1*vx1 : 0.f);
        float sy = vy0 + (v1 ? vy1 : 0.f);
        float qy = vy0*vy0 + (v1 ? vy1*vy1 : 0.f);
        sx = wredsum(sx); qx = wredsum(qx);
        sy = wredsum(sy); qy = wredsum(qy);
        if (tx == 0) {
            g_ps1[o0*9600 + blk] = sx;  g_pq1[o0*9600 + blk] = qx;
            g_ps1[(o0+1)*9600 + blk] = sy;  g_pq1[(o0+1)*9600 + blk] = qy;
        }
    }
}

// ---------------- BN final reductions (deterministic) ----------------
__device__ __forceinline__ void bnsum_body(const float* ps, const float* pq,
                                           int cnt, int off) {
    int o = blockIdx.x;
    __shared__ float sh[512];
    float s = 0.f, q = 0.f;
    for (int i = threadIdx.x; i < cnt; i += 256) {
        s += ps[o*cnt + i];
        q += pq[o*cnt + i];
    }
    sh[threadIdx.x] = s; sh[256 + threadIdx.x] = q;
    __syncthreads();
    for (int st = 128; st; st >>= 1) {
        if (threadIdx.x < st) {
            sh[threadIdx.x] += sh[threadIdx.x + st];
            sh[256 + threadIdx.x] += sh[256 + threadIdx.x + st];
        }
        __syncthreads();
    }
    if (threadIdx.x == 0) {
        g_stats[off + o] = sh[0];
        g_stats[off + 64 + o] = sh[256];
    }
}
__global__ void k_bnsum1() { bnsum_body(g_ps1, g_pq1, 9600, 0); }
__global__ void k_bnsum2() { bnsum_body(g_ps2, g_pq2, 1920, 128); }

// ---------------- K6: temporal conv + fused BN1-apply + BN2-partials --------
__global__ void __launch_bounds__(256) k_tcn(const float* __restrict__ Wt,
                                             const float* __restrict__ bt,
                                             const float* __restrict__ x,
                                             const float* __restrict__ g1,
                                             const float* __restrict__ b1,
                                             float* __restrict__ out) {
    __shared__ float ys[8 * 456];
    __shared__ __align__(16) float wsm[8 * 9 * 64];
    __shared__ float csc[64], csh[64];
    int n = blockIdx.y;
    int tile0 = blockIdx.x * 256;
    int tid = threadIdx.x;
    int ty = tid >> 5, tx = tid & 31;
    int ob = ty * 8;
    if (tid < 64) {
        const float inv = 1.f / BN_CNT;
        float mu  = g_stats[tid] * inv;
        float var = fmaf(-mu, mu, g_stats[64 + tid] * inv);
        float sc  = rsqrtf(var + 1e-5f) * g1[tid];
        csc[tid] = sc;
        csh[tid] = fmaf(-mu, sc, b1[tid]);
    }
    ull acc2[4][8];
    #pragma unroll
    for (int a = 0; a < 4; a++)
        #pragma unroll
        for (int j = 0; j < 8; j++) acc2[a][j] = 0ull;
    __syncthreads();

    for (int c0 = 0; c0 < 64; c0 += 8) {
        __syncthreads();
        for (int i = tid; i < 8 * 456; i += 256) {
            int c = i / 456, off = i - c * 456;
            int tw = tile0 - 100 + off;
            int cc = c0 + c;
            float v = 0.f;
            if (tw >= 0 && tw < TV) {
                int gi = (n * CC + cc) * TV + tw;
                float raw = g_y1[gi];
                v = fmaf(raw, csc[cc], csh[cc]) + x[gi];
                v = fmaxf(v, 0.f);
            }
            ys[i] = v;
        }
        for (int i = tid; i < 8 * 9 * 64; i += 256) {
            int o = i & 63, ck = i >> 6;
            int c = ck / 9, kt = ck - c * 9;
            wsm[i] = Wt[(o * 64 + c0 + c) * 9 + kt];
        }
        __syncthreads();
        for (int c = 0; c < 8; c++) {
            #pragma unroll 3
            for (int kt = 0; kt < 9; kt++) {
                int ybase = c * 456 + 100 + 25 * (kt - 4) + tx;
                ull yd[8];
                #pragma unroll
                for (int j = 0; j < 8; j++) yd[j] = dup2(ys[ybase + 32 * j]);
                const ulonglong2* wp2 = (const ulonglong2*)(wsm + (c * 9 + kt) * 64 + ob);
                ulonglong2 wA = wp2[0];
                ulonglong2 wB = wp2[1];
                #pragma unroll
                for (int j = 0; j < 8; j++) {
                    acc2[0][j] = fma2(wA.x, yd[j], acc2[0][j]);
                    acc2[1][j] = fma2(wA.y, yd[j], acc2[1][j]);
                    acc2[2][j] = fma2(wB.x, yd[j], acc2[2][j]);
                    acc2[3][j] = fma2(wB.y, yd[j], acc2[3][j]);
                }
            }
        }
    }
    int blk = n * 30 + blockIdx.x;
    #pragma unroll
    for (int a = 0; a < 4; a++) {
        int o0 = ob + 2*a;
        float b0 = bt[o0], b1v = bt[o0+1];
        float sx = 0.f, qx = 0.f, sy = 0.f, qy = 0.f;
        #pragma unroll
        for (int j = 0; j < 8; j++) {
            int tw = tile0 + tx + 32 * j;
            if (tw < TV) {
                float2 f = unpk(acc2[a][j]);
                float vx = f.x + b0, vy = f.y + b1v;
                out[(size_t)(n * OCn + o0  ) * TV + tw] = vx;
                out[(size_t)(n * OCn + o0+1) * TV + tw] = vy;
                sx += vx; qx += vx*vx;
                sy += vy; qy += vy*vy;
            }
        }
        sx = wredsum(sx); qx = wredsum(qx);
        sy = wredsum(sy); qy = wredsum(qy);
        if (tx == 0) {
            g_ps2[o0*1920 + blk] = sx;  g_pq2[o0*1920 + blk] = qx;
            g_ps2[(o0+1)*1920 + blk] = sy;  g_pq2[(o0+1)*1920 + blk] = qy;
        }
    }
}

// ---------------- BN2 apply + residual + relu ----------------
__global__ void k_bn2(float* __restrict__ out, const float* __restrict__ x,
                      const float* __restrict__ g2, const float* __restrict__ b2) {
    int idx = blockIdx.x * 256 + threadIdx.x;
    if (idx >= YSZ) return;
    int c = (idx / TV) & 63;
    const float inv = 1.f / BN_CNT;
    float mu  = g_stats[128 + c] * inv;
    float var = fmaf(-mu, mu, g_stats[192 + c] * inv);
    float sc  = rsqrtf(var + 1e-5f) * g2[c];
    float v   = (out[idx] - mu) * sc + b2[c] + x[idx];
    out[idx] = fmaxf(v, 0.f);
}

// ---------------- adj passthrough ----------------
__global__ void k_copyadj(const float* __restrict__ adj, float* __restrict__ out, int count) {
    int i = blockIdx.x * 256 + threadIdx.x;
    if (i < count) out[YSZ + i] = adj[i];
}

// ---------------- launch ----------------
extern "C" void kernel_launch(void* const* d_in, const int* in_sizes, int n_in,
                              void* d_out, int out_size) {
    const float* x   = (const float*)d_in[0];
    const float* adj = (const float*)d_in[1];
    const float* PA  = (const float*)d_in[2];
    const float* Wa  = (const float*)d_in[3];
    const float* ba  = (const float*)d_in[4];
    const float* Wb  = (const float*)d_in[5];
    const float* bb  = (const float*)d_in[6];
    const float* Wd  = (const float*)d_in[7];
    const float* bd  = (const float*)d_in[8];
    const float* g1  = (const float*)d_in[9];
    const float* b1  = (const float*)d_in[10];
    const float* Wt  = (const float*)d_in[11];
    const float* bt  = (const float*)d_in[12];
    const float* g2  = (const float*)d_in[13];
    const float* b2  = (const float*)d_in[14];
    float* out = (float*)d_out;

    static int smem_set = 0;
    if (!smem_set) {
        cudaFuncSetAttribute(k_gcn, cudaFuncAttributeMaxDynamicSharedMemorySize,
                             GS_TOT * sizeof(float));
        smem_set = 1;
    }

    // copyadj first so the profiler's 4th launch lands on k_gcn
    int adjcount = out_size - YSZ;
    if (adjcount > 0) {
        if (adjcount > 3 * VV * VV) adjcount = 3 * VV * VV;
        k_copyadj<<<8, 256>>>(adj, out, adjcount);
    }

    k_projab<<<dim3(8, 64), 256>>>(x, Wa, ba, Wb, bb);
    k_scoreS<<<192, 640>>>(adj, PA);
    k_gcn<<<dim3(150, 64), 256, GS_TOT * sizeof(float)>>>(x, Wd, bd);

    k_bnsum1<<<64, 256>>>();

    k_tcn<<<dim3(30, 64), 256>>>(Wt, bt, x, g1, b1, out);

    k_bnsum2<<<64, 256>>>();
    k_bn2<<<(YSZ + 255) / 256, 256>>>(out, x, g2, b2);
}